// round 13
// baseline (speedup 1.0000x reference)
#include <cuda_runtime.h>
#include <math.h>
#include <stdint.h>

#define T_STEPS 1024
#define BATCH   64
#define VDIM    256
#define HIDDEN  512
#define CPB     64                 // columns per CTA
#define BG      4                  // batches per group
#define CBLKS   8                  // CTAs per group
#define GROUPS  16                 // batch groups
#define NB      128                // CTAs
#define RT      256
#define PSTR    21                 // partials row stride (16 data + 5 pad)
#define REC_SMEM (120 * 1024)      // force 1 CTA/SM

// Scratch (device globals: allocation APIs are forbidden)
__device__ float g_P [(size_t)T_STEPS * BATCH * HIDDEN];
__device__ float g_S0[(size_t)T_STEPS * BATCH * HIDDEN];
__device__ float g_Hbuf[2][GROUPS][BG * HIDDEN];

// One u64 of 8 per-CTA byte-flags per group; each group on its own 128B line.
struct GFlag { unsigned long long w; unsigned long long pad[15]; };
__device__ GFlag g_flag[GROUPS];

#define FMA2(acc, w, h) \
    asm("fma.rn.f32x2 %0, %1, %2, %0;" : "+l"(acc) : "l"(w), "l"(h))
#define PACKF2(d, x) \
    asm("mov.b64 %0, {%1, %1};" : "=l"(d) : "f"(x))

// ---------------------------------------------------------------------------
// GEMM (f32x2): C[m][n] = sum_k A[m][k]*W[n*ldw+k] + bias[n]
// ---------------------------------------------------------------------------
__global__ __launch_bounds__(256) void gemm_awt(
    const float* __restrict__ A, const float* __restrict__ W,
    const float* __restrict__ bias, float* __restrict__ C,
    int K, int ldw)
{
    __shared__ float As[8][128];
    __shared__ float Ws[8][128];

    const int tid = threadIdx.x;
    const int m0 = blockIdx.y * 128;
    const int n0 = blockIdx.x * 128;
    const int tx = tid & 15;
    const int ty = tid >> 4;
    const int rowL = tid >> 1;
    const int colL = (tid & 1) * 4;

    const float* Ag = A + (size_t)(m0 + rowL) * K + colL;
    const float* Wg = W + (size_t)(n0 + rowL) * ldw + colL;

    long long accp[8][4];
#pragma unroll
    for (int i = 0; i < 8; ++i)
#pragma unroll
        for (int jp = 0; jp < 4; ++jp) accp[i][jp] = 0;

    float4 av = *(const float4*)(Ag);
    float4 wv = *(const float4*)(Wg);

    for (int k0 = 0; k0 < K; k0 += 8) {
        __syncthreads();
        As[colL + 0][rowL] = av.x; As[colL + 1][rowL] = av.y;
        As[colL + 2][rowL] = av.z; As[colL + 3][rowL] = av.w;
        Ws[colL + 0][rowL] = wv.x; Ws[colL + 1][rowL] = wv.y;
        Ws[colL + 2][rowL] = wv.z; Ws[colL + 3][rowL] = wv.w;
        __syncthreads();
        if (k0 + 8 < K) {
            av = *(const float4*)(Ag + k0 + 8);
            wv = *(const float4*)(Wg + k0 + 8);
        }
#pragma unroll
        for (int k = 0; k < 8; ++k) {
            float4 a0 = *(const float4*)&As[k][ty * 8];
            float4 a1 = *(const float4*)&As[k][ty * 8 + 4];
            longlong2 b01 = *(const longlong2*)&Ws[k][tx * 8];
            longlong2 b23 = *(const longlong2*)&Ws[k][tx * 8 + 4];
            float a[8] = {a0.x, a0.y, a0.z, a0.w, a1.x, a1.y, a1.z, a1.w};
#pragma unroll
            for (int i = 0; i < 8; ++i) {
                long long a2; PACKF2(a2, a[i]);
                FMA2(accp[i][0], a2, b01.x);
                FMA2(accp[i][1], a2, b01.y);
                FMA2(accp[i][2], a2, b23.x);
                FMA2(accp[i][3], a2, b23.y);
            }
        }
    }

    float bn[8];
#pragma unroll
    for (int j = 0; j < 8; ++j) bn[j] = bias[n0 + tx * 8 + j];

    float* Cp = C + (size_t)(m0 + ty * 8) * HIDDEN + n0 + tx * 8;
#pragma unroll
    for (int i = 0; i < 8; ++i) {
        float4 v0, v1;
        float2 f0 = *reinterpret_cast<float2*>(&accp[i][0]);
        float2 f1 = *reinterpret_cast<float2*>(&accp[i][1]);
        float2 f2 = *reinterpret_cast<float2*>(&accp[i][2]);
        float2 f3 = *reinterpret_cast<float2*>(&accp[i][3]);
        v0.x = f0.x + bn[0]; v0.y = f0.y + bn[1];
        v0.z = f1.x + bn[2]; v0.w = f1.y + bn[3];
        v1.x = f2.x + bn[4]; v1.y = f2.y + bn[5];
        v1.z = f3.x + bn[6]; v1.w = f3.y + bn[7];
        *(float4*)(Cp + (size_t)i * HIDDEN)     = v0;
        *(float4*)(Cp + (size_t)i * HIDDEN + 4) = v1;
    }
}

// ---------------------------------------------------------------------------
// Flag helpers: 8 byte-flags in one u64. Value semantics: a CTA's byte holds
// its publish count: 1 after the h0 prologue, t+2 after publishing step t's h.
// Consumer at step t needs all bytes in {t+1, t+2} (mod 256; skew <= 1 step).
// ---------------------------------------------------------------------------
__device__ __forceinline__ void flag_wait(const unsigned long long* fp, int t)
{
    unsigned e1 = (unsigned)((t + 1) & 255) * 0x01010101u;
    unsigned e2 = (unsigned)((t + 2) & 255) * 0x01010101u;
    for (;;) {
        unsigned long long v = *(volatile const unsigned long long*)fp;
        unsigned lo = (unsigned)v, hi = (unsigned)(v >> 32);
        unsigned ok = (__vcmpeq4(lo, e1) | __vcmpeq4(lo, e2)) &
                      (__vcmpeq4(hi, e1) | __vcmpeq4(hi, e2));
        if (ok == 0xFFFFFFFFu) break;
    }
    __threadfence();   // acquire: h reads below see peers' published data
}

// ---------------------------------------------------------------------------
// Persistent recurrence, register-h + byte-flag exchange.
// ---------------------------------------------------------------------------
__global__ __launch_bounds__(RT, 1) void rnn_rec(
    const float* __restrict__ P,
    const float* __restrict__ Wfull, int ldw, int koff,
    const float* __restrict__ h0,
    float* __restrict__ states,
    float* __restrict__ last)
{
    extern __shared__ float sh[];
    float* Ps = sh;                        // [256][PSTR]

    const int tid  = threadIdx.x;
    const int cblk = blockIdx.x & (CBLKS - 1);
    const int grp  = blockIdx.x >> 3;
    const int j0   = cblk * CPB;
    const int kc   = tid >> 4;             // 0..15 (uniform per half-warp)
    const int jg   = tid & 15;             // 0..15
    const int rb   = tid >> 6;             // reduce role: batch 0..3
    const int rcol = tid & 63;
    const int rj   = j0 + rcol;
    const int rbg  = grp * BG + rb;

    const unsigned long long* fword = &g_flag[grp].w;
    volatile unsigned char* myflag =
        (volatile unsigned char*)fword + cblk;

    // Prologue: publish our 64-col slice of h0 into buffer 1, signal flag=1.
    g_Hbuf[1][grp][rb * HIDDEN + rj] = h0[(size_t)rbg * HIDDEN + rj];
    __syncthreads();
    if (tid == 0) { __threadfence(); *myflag = (unsigned char)1; }

    // Weights in registers: rows j0 + jg*4 + c, k = kc*32 .. +32.
    union LLF { float4 f; longlong2 l; };
    longlong2 wr[4][8];
#pragma unroll
    for (int c = 0; c < 4; ++c) {
        const float* wp = Wfull + (size_t)(j0 + jg * 4 + c) * ldw + koff + kc * 32;
#pragma unroll
        for (int i = 0; i < 8; ++i) {
            LLF u; u.f = *(const float4*)(wp + i * 4);
            wr[c][i] = u.l;
        }
    }

    for (int t = 0; t < T_STEPS; ++t) {
        float p = P[((size_t)t * BATCH + rbg) * HIDDEN + rj];  // before poll

        flag_wait(fword, t);

        // h_{t-1} straight from L2 into registers; 2 batches at a time.
        const float* hc = &g_Hbuf[(t + 1) & 1][grp][kc * 32];
        long long acc[4][4];
#pragma unroll
        for (int c = 0; c < 4; ++c)
#pragma unroll
            for (int b = 0; b < 4; ++b) acc[c][b] = 0;

#pragma unroll
        for (int pr = 0; pr < 2; ++pr) {
            LLF h[2][8];
#pragma unroll
            for (int b = 0; b < 2; ++b)
#pragma unroll
                for (int i = 0; i < 8; ++i)
                    h[b][i].f = __ldcg((const float4*)(hc + (pr * 2 + b) * HIDDEN + i * 4));
#pragma unroll
            for (int i = 0; i < 8; ++i)
#pragma unroll
                for (int c = 0; c < 4; ++c) {
                    longlong2 w = wr[c][i];
                    FMA2(acc[c][pr * 2 + 0], w.x, h[0][i].l.x);
                    FMA2(acc[c][pr * 2 + 0], w.y, h[0][i].l.y);
                    FMA2(acc[c][pr * 2 + 1], w.x, h[1][i].l.x);
                    FMA2(acc[c][pr * 2 + 1], w.y, h[1][i].l.y);
                }
        }

        // Partials to smem: out o = b*64 + jg*4 + c.
#pragma unroll
        for (int c = 0; c < 4; ++c)
#pragma unroll
            for (int b = 0; b < 4; ++b) {
                float2 f = *reinterpret_cast<float2*>(&acc[c][b]);
                Ps[(b * 64 + jg * 4 + c) * PSTR + kc] = f.x + f.y;
            }
        __syncthreads();

        // Reduce: thread owns output (rb, rcol).
        float s = 0.f;
        const float* pr2 = Ps + tid * PSTR;
#pragma unroll
        for (int i = 0; i < 16; ++i) s += pr2[i];
        float hv = tanhf(p + s);

        if (t == T_STEPS - 1) {
            states[((size_t)t * BATCH + rbg) * HIDDEN + rj] = hv;
            last[(size_t)rbg * HIDDEN + rj] = hv;
            break;
        }

        // Publish h FIRST (critical path), then signal, then states.
        g_Hbuf[t & 1][grp][rb * HIDDEN + rj] = hv;
        __syncthreads();   // all h STGs issued; also protects Ps reuse
        if (tid == 0) {
            __threadfence();
            *myflag = (unsigned char)((t + 2) & 255);
        }
        states[((size_t)t * BATCH + rbg) * HIDDEN + rj] = hv;  // off critical path
    }
}

// ---------------------------------------------------------------------------
extern "C" void kernel_launch(void* const* d_in, const int* in_sizes, int n_in,
                              void* d_out, int out_size)
{
    (void)in_sizes; (void)n_in; (void)out_size;
    const float* inputs = (const float*)d_in[0];
    const float* H      = (const float*)d_in[1];
    const float* W_net  = (const float*)d_in[2];
    const float* b_net  = (const float*)d_in[3];
    const float* W_deep = (const float*)d_in[4];
    const float* b_deep = (const float*)d_in[5];

    float* out     = (float*)d_out;
    float* states1 = out;
    float* lasts   = out + (size_t)T_STEPS * BATCH * HIDDEN;

    float *P, *S0;
    cudaGetSymbolAddress((void**)&P,  g_P);
    cudaGetSymbolAddress((void**)&S0, g_S0);

    cudaFuncSetAttribute(rnn_rec, cudaFuncAttributeMaxDynamicSharedMemorySize, REC_SMEM);

    dim3 ggrid(HIDDEN / 128, (T_STEPS * BATCH) / 128);

    gemm_awt<<<ggrid, 256>>>(inputs, W_net, b_net, P, VDIM, VDIM + HIDDEN);
    rnn_rec<<<NB, RT, REC_SMEM>>>(P, W_net, VDIM + HIDDEN, VDIM, H, S0, lasts);

    gemm_awt<<<ggrid, 256>>>(S0, W_deep, b_deep, P, HIDDEN, 2 * HIDDEN);
    rnn_rec<<<NB, RT, REC_SMEM>>>(P, W_deep, 2 * HIDDEN, HIDDEN,
                                  H + BATCH * HIDDEN, states1,
                                  lasts + BATCH * HIDDEN);
}

// round 16
// speedup vs baseline: 1.1323x; 1.1323x over previous
#include <cuda_runtime.h>
#include <math.h>
#include <stdint.h>

#define T_STEPS 1024
#define BATCH   64
#define VDIM    256
#define HIDDEN  512
#define CPB     64                 // columns per CTA
#define BG      4                  // batches per group
#define CBLKS   8                  // CTAs per group
#define GROUPS  16                 // batch groups
#define NB      128                // CTAs
#define RT      256
#define PSTR    21                 // partials row stride (16 data + 5 pad)
#define REC_SMEM (120 * 1024)      // force 1 CTA/SM

// Scratch (device globals: allocation APIs are forbidden)
__device__ float g_P [(size_t)T_STEPS * BATCH * HIDDEN];
__device__ float g_S0[(size_t)T_STEPS * BATCH * HIDDEN];
__device__ float g_Hbuf[2][GROUPS][BG * HIDDEN];

struct PadU { unsigned v; unsigned pad[63]; };
__device__ PadU g_count[GROUPS];
__device__ PadU g_gen[GROUPS];

#define FMA2(acc, w, h) \
    asm("fma.rn.f32x2 %0, %1, %2, %0;" : "+l"(acc) : "l"(w), "l"(h))
#define PACKF2(d, x) \
    asm("mov.b64 %0, {%1, %1};" : "=l"(d) : "f"(x))

// ---------------------------------------------------------------------------
// GEMM (f32x2): C[m][n] = sum_k A[m][k]*W[n*ldw+k] + bias[n]
// (validated in rounds 10 and 13)
// ---------------------------------------------------------------------------
__global__ __launch_bounds__(256) void gemm_awt(
    const float* __restrict__ A, const float* __restrict__ W,
    const float* __restrict__ bias, float* __restrict__ C,
    int K, int ldw)
{
    __shared__ float As[8][128];
    __shared__ float Ws[8][128];

    const int tid = threadIdx.x;
    const int m0 = blockIdx.y * 128;
    const int n0 = blockIdx.x * 128;
    const int tx = tid & 15;
    const int ty = tid >> 4;
    const int rowL = tid >> 1;
    const int colL = (tid & 1) * 4;

    const float* Ag = A + (size_t)(m0 + rowL) * K + colL;
    const float* Wg = W + (size_t)(n0 + rowL) * ldw + colL;

    long long accp[8][4];
#pragma unroll
    for (int i = 0; i < 8; ++i)
#pragma unroll
        for (int jp = 0; jp < 4; ++jp) accp[i][jp] = 0;

    float4 av = *(const float4*)(Ag);
    float4 wv = *(const float4*)(Wg);

    for (int k0 = 0; k0 < K; k0 += 8) {
        __syncthreads();
        As[colL + 0][rowL] = av.x; As[colL + 1][rowL] = av.y;
        As[colL + 2][rowL] = av.z; As[colL + 3][rowL] = av.w;
        Ws[colL + 0][rowL] = wv.x; Ws[colL + 1][rowL] = wv.y;
        Ws[colL + 2][rowL] = wv.z; Ws[colL + 3][rowL] = wv.w;
        __syncthreads();
        if (k0 + 8 < K) {
            av = *(const float4*)(Ag + k0 + 8);
            wv = *(const float4*)(Wg + k0 + 8);
        }
#pragma unroll
        for (int k = 0; k < 8; ++k) {
            float4 a0 = *(const float4*)&As[k][ty * 8];
            float4 a1 = *(const float4*)&As[k][ty * 8 + 4];
            longlong2 b01 = *(const longlong2*)&Ws[k][tx * 8];
            longlong2 b23 = *(const longlong2*)&Ws[k][tx * 8 + 4];
            float a[8] = {a0.x, a0.y, a0.z, a0.w, a1.x, a1.y, a1.z, a1.w};
#pragma unroll
            for (int i = 0; i < 8; ++i) {
                long long a2; PACKF2(a2, a[i]);
                FMA2(accp[i][0], a2, b01.x);
                FMA2(accp[i][1], a2, b01.y);
                FMA2(accp[i][2], a2, b23.x);
                FMA2(accp[i][3], a2, b23.y);
            }
        }
    }

    float bn[8];
#pragma unroll
    for (int j = 0; j < 8; ++j) bn[j] = bias[n0 + tx * 8 + j];

    float* Cp = C + (size_t)(m0 + ty * 8) * HIDDEN + n0 + tx * 8;
#pragma unroll
    for (int i = 0; i < 8; ++i) {
        float4 v0, v1;
        float2 f0 = *reinterpret_cast<float2*>(&accp[i][0]);
        float2 f1 = *reinterpret_cast<float2*>(&accp[i][1]);
        float2 f2 = *reinterpret_cast<float2*>(&accp[i][2]);
        float2 f3 = *reinterpret_cast<float2*>(&accp[i][3]);
        v0.x = f0.x + bn[0]; v0.y = f0.y + bn[1];
        v0.z = f1.x + bn[2]; v0.w = f1.y + bn[3];
        v1.x = f2.x + bn[4]; v1.y = f2.y + bn[5];
        v1.z = f3.x + bn[6]; v1.w = f3.y + bn[7];
        *(float4*)(Cp + (size_t)i * HIDDEN)     = v0;
        *(float4*)(Cp + (size_t)i * HIDDEN + 4) = v1;
    }
}

// ---------------------------------------------------------------------------
// Barrier helpers (R12 protocol, fences fused into release/acquire atomics).
//   arrive: after __syncthreads, tid0 does atom.add.release.gpu — the release
//   publishes the whole CTA's prior stores (h publish) to acquirers.
//   last arriver: reset count (plain), then st.release.gpu of gen (orders reset).
//   consumers: all-thread ld.acquire.gpu poll.
// ---------------------------------------------------------------------------
__device__ __forceinline__ void group_arrive_release(int grp, unsigned gen)
{
    unsigned tk;
    asm volatile("atom.add.release.gpu.global.u32 %0, [%1], %2;"
                 : "=r"(tk) : "l"(&g_count[grp].v), "r"(1u) : "memory");
    if (tk == CBLKS - 1u) {
        *(volatile unsigned*)&g_count[grp].v = 0u;
        asm volatile("st.release.gpu.global.u32 [%0], %1;"
                     :: "l"(&g_gen[grp].v), "r"(gen + 1u) : "memory");
    }
}

// ---------------------------------------------------------------------------
// Persistent recurrence (R12 structure, proven correct):
//   thread: kc = tid>>4 (warp-uniform 32-wide k-chunk), jg = tid&15.
//   w[4 cols][32 k] in registers; h loaded per step straight from L2
//   (__ldcg, half-warp broadcast-coalesced); partial reduce via padded smem.
// ---------------------------------------------------------------------------
__global__ __launch_bounds__(RT, 1) void rnn_rec(
    const float* __restrict__ P,
    const float* __restrict__ Wfull, int ldw, int koff,
    const float* __restrict__ h0,
    float* __restrict__ states,
    float* __restrict__ last)
{
    extern __shared__ float sh[];
    float* Ps = sh;                        // [256][PSTR]

    const int tid  = threadIdx.x;
    const int cblk = blockIdx.x & (CBLKS - 1);
    const int grp  = blockIdx.x >> 3;
    const int j0   = cblk * CPB;
    const int kc   = tid >> 4;             // 0..15 (uniform per half-warp)
    const int jg   = tid & 15;             // 0..15
    const int rb   = tid >> 6;             // reduce role: batch 0..3
    const int rcol = tid & 63;
    const int rj   = j0 + rcol;
    const int rbg  = grp * BG + rb;

    // Weights in registers: rows j0 + jg*4 + c, k = kc*32 .. +32.
    union LLF { float4 f; longlong2 l; };
    longlong2 wr[4][8];
#pragma unroll
    for (int c = 0; c < 4; ++c) {
        const float* wp = Wfull + (size_t)(j0 + jg * 4 + c) * ldw + koff + kc * 32;
#pragma unroll
        for (int i = 0; i < 8; ++i) {
            LLF u; u.f = *(const float4*)(wp + i * 4);
            wr[c][i] = u.l;
        }
    }

    // Publish our 64-col slice of h0 into buffer 1 (read at t=0).
    unsigned gen = *(volatile unsigned*)&g_gen[grp].v;   // before our arrive
    g_Hbuf[1][grp][rb * HIDDEN + rj] = h0[(size_t)rbg * HIDDEN + rj];
    __syncthreads();
    if (tid == 0) group_arrive_release(grp, gen);

    for (int t = 0; t < T_STEPS; ++t) {
        float p = P[((size_t)t * BATCH + rbg) * HIDDEN + rj];  // before poll

        // All threads: acquire-poll the group generation.
        {
            unsigned cur;
            do {
                asm volatile("ld.acquire.gpu.global.u32 %0, [%1];"
                             : "=r"(cur) : "l"(&g_gen[grp].v) : "memory");
            } while (cur == gen);
            gen = cur;
        }

        // h_{t-1} straight from L2 into registers; 2 batches at a time.
        const float* hc = &g_Hbuf[(t + 1) & 1][grp][kc * 32];
        long long acc[4][4];
#pragma unroll
        for (int c = 0; c < 4; ++c)
#pragma unroll
            for (int b = 0; b < 4; ++b) acc[c][b] = 0;

#pragma unroll
        for (int pr = 0; pr < 2; ++pr) {
            LLF h[2][8];
#pragma unroll
            for (int b = 0; b < 2; ++b)
#pragma unroll
                for (int i = 0; i < 8; ++i)
                    h[b][i].f = __ldcg((const float4*)(hc + (pr * 2 + b) * HIDDEN + i * 4));
#pragma unroll
            for (int i = 0; i < 8; ++i)
#pragma unroll
                for (int c = 0; c < 4; ++c) {
                    longlong2 w = wr[c][i];
                    FMA2(acc[c][pr * 2 + 0], w.x, h[0][i].l.x);
                    FMA2(acc[c][pr * 2 + 0], w.y, h[0][i].l.y);
                    FMA2(acc[c][pr * 2 + 1], w.x, h[1][i].l.x);
                    FMA2(acc[c][pr * 2 + 1], w.y, h[1][i].l.y);
                }
        }

        // Partials to smem: out o = b*64 + jg*4 + c.
#pragma unroll
        for (int c = 0; c < 4; ++c)
#pragma unroll
            for (int b = 0; b < 4; ++b) {
                float2 f = *reinterpret_cast<float2*>(&acc[c][b]);
                Ps[(b * 64 + jg * 4 + c) * PSTR + kc] = f.x + f.y;
            }
        __syncthreads();

        // Reduce: thread owns output (rb, rcol).
        float s = 0.f;
        const float* pr2 = Ps + tid * PSTR;
#pragma unroll
        for (int i = 0; i < 16; ++i) s += pr2[i];
        float hv = tanhf(p + s);

        states[((size_t)t * BATCH + rbg) * HIDDEN + rj] = hv;
        if (t == T_STEPS - 1) {
            last[(size_t)rbg * HIDDEN + rj] = hv;
            break;
        }
        g_Hbuf[t & 1][grp][rb * HIDDEN + rj] = hv;

        __syncthreads();     // h published CTA-wide; also protects Ps reuse
        if (tid == 0) group_arrive_release(grp, gen);
    }
}

// ---------------------------------------------------------------------------
extern "C" void kernel_launch(void* const* d_in, const int* in_sizes, int n_in,
                              void* d_out, int out_size)
{
    (void)in_sizes; (void)n_in; (void)out_size;
    const float* inputs = (const float*)d_in[0];
    const float* H      = (const float*)d_in[1];
    const float* W_net  = (const float*)d_in[2];
    const float* b_net  = (const float*)d_in[3];
    const float* W_deep = (const float*)d_in[4];
    const float* b_deep = (const float*)d_in[5];

    float* out     = (float*)d_out;
    float* states1 = out;
    float* lasts   = out + (size_t)T_STEPS * BATCH * HIDDEN;

    float *P, *S0;
    cudaGetSymbolAddress((void**)&P,  g_P);
    cudaGetSymbolAddress((void**)&S0, g_S0);

    cudaFuncSetAttribute(rnn_rec, cudaFuncAttributeMaxDynamicSharedMemorySize, REC_SMEM);

    dim3 ggrid(HIDDEN / 128, (T_STEPS * BATCH) / 128);

    gemm_awt<<<ggrid, 256>>>(inputs, W_net, b_net, P, VDIM, VDIM + HIDDEN);
    rnn_rec<<<NB, RT, REC_SMEM>>>(P, W_net, VDIM + HIDDEN, VDIM, H, S0, lasts);

    gemm_awt<<<ggrid, 256>>>(S0, W_deep, b_deep, P, HIDDEN, 2 * HIDDEN);
    rnn_rec<<<NB, RT, REC_SMEM>>>(P, W_deep, 2 * HIDDEN, HIDDEN,
                                  H + BATCH * HIDDEN, states1,
                                  lasts + BATCH * HIDDEN);
}